// round 2
// baseline (speedup 1.0000x reference)
#include <cuda_runtime.h>

#define OUT_DIM 4096
#define IN_DIM  4096
#define M_DIM   8192
#define CB_BLK  8

// 64 MB scratch for the decompressed, scale-folded weight matrix [OUT, IN] row-major.
__device__ float g_W[(size_t)OUT_DIM * IN_DIM];

// ---------------------------------------------------------------------------
// Kernel 1: VQ decompress + fold scale.
// W[j*8 + t] = centroids[labels[j]][t] * scale[(j*8 + t) % IN_DIM]
// One thread per 8-element codebook block. labels is int32 (JAX downgrades
// int64 without x64 mode). Mask &0xFF is identity for valid labels (0..255)
// and guards against OOB under any dtype surprise.
// ---------------------------------------------------------------------------
__global__ void __launch_bounds__(256) decompress_kernel(
    const int* __restrict__ labels,
    const float* __restrict__ centroids,
    const float* __restrict__ scale)
{
    int j = blockIdx.x * blockDim.x + threadIdx.x;   // 0 .. 2097151
    int lab = labels[j] & 0xFF;
    const float4* c = reinterpret_cast<const float4*>(centroids + (size_t)lab * CB_BLK);
    float4 c0 = c[0];
    float4 c1 = c[1];
    int k = (j * CB_BLK) & (IN_DIM - 1);             // column start, multiple of 8
    const float4* s = reinterpret_cast<const float4*>(scale + k);
    float4 s0 = s[0];
    float4 s1 = s[1];
    float4 w0 = make_float4(c0.x * s0.x, c0.y * s0.y, c0.z * s0.z, c0.w * s0.w);
    float4 w1 = make_float4(c1.x * s1.x, c1.y * s1.y, c1.z * s1.z, c1.w * s1.w);
    float4* dst = reinterpret_cast<float4*>(g_W + (size_t)j * CB_BLK);
    dst[0] = w0;
    dst[1] = w1;
}

// ---------------------------------------------------------------------------
// Kernel 2: fp32 SGEMM  C[M,N] = A[M,K] @ B[N,K]^T + bias
//   A = x (row-major, K contiguous), B = g_W (row-major, K contiguous)
// Tiling: 128x128 block tile, BK=16, 256 threads, 8x8 register micro-tile.
// ---------------------------------------------------------------------------
#define BM 128
#define BN 128
#define BK 16
#define TM 8
#define TN 8

__global__ void __launch_bounds__(256) sgemm_kernel(
    const float* __restrict__ A,
    const float* __restrict__ bias,
    float* __restrict__ C)
{
    const float* B = g_W;

    __shared__ float As[BK][BM];
    __shared__ float Bs[BK][BN];

    const int bm = blockIdx.y * BM;
    const int bn = blockIdx.x * BN;
    const int tid = threadIdx.x;

    // Global->smem load mapping: tile is 128 rows x 16 cols = 512 float4.
    // Each thread loads 2 float4 from A and 2 from B per K-step.
    const int l_row  = tid >> 2;          // 0..63 (second row = +64)
    const int l_col4 = (tid & 3) << 2;    // float col within tile: 0,4,8,12

    // Compute mapping: 16x16 thread grid of 8x8 micro-tiles.
    const int trow = (tid >> 4) * TM;     // 0..120
    const int tcol = (tid & 15) * TN;     // 0..120

    float acc[TM][TN];
    #pragma unroll
    for (int i = 0; i < TM; i++)
        #pragma unroll
        for (int j = 0; j < TN; j++)
            acc[i][j] = 0.0f;

    float a_reg[TM];
    float b_reg[TN];

    const float* A_base = A + (size_t)(bm + l_row) * IN_DIM + l_col4;
    const float* B_base = B + (size_t)(bn + l_row) * IN_DIM + l_col4;

    for (int k0 = 0; k0 < IN_DIM; k0 += BK) {
        // Load A tile (stored K-transposed) and B tile (stored K-transposed)
        #pragma unroll
        for (int r = 0; r < 2; r++) {
            const int row = l_row + r * 64;
            float4 va = *reinterpret_cast<const float4*>(A_base + (size_t)r * 64 * IN_DIM + k0);
            As[l_col4 + 0][row] = va.x;
            As[l_col4 + 1][row] = va.y;
            As[l_col4 + 2][row] = va.z;
            As[l_col4 + 3][row] = va.w;
            float4 vb = *reinterpret_cast<const float4*>(B_base + (size_t)r * 64 * IN_DIM + k0);
            Bs[l_col4 + 0][row] = vb.x;
            Bs[l_col4 + 1][row] = vb.y;
            Bs[l_col4 + 2][row] = vb.z;
            Bs[l_col4 + 3][row] = vb.w;
        }
        __syncthreads();

        #pragma unroll
        for (int kk = 0; kk < BK; kk++) {
            #pragma unroll
            for (int i = 0; i < TM; i += 4) {
                float4 v = *reinterpret_cast<const float4*>(&As[kk][trow + i]);
                a_reg[i + 0] = v.x; a_reg[i + 1] = v.y;
                a_reg[i + 2] = v.z; a_reg[i + 3] = v.w;
            }
            #pragma unroll
            for (int j = 0; j < TN; j += 4) {
                float4 v = *reinterpret_cast<const float4*>(&Bs[kk][tcol + j]);
                b_reg[j + 0] = v.x; b_reg[j + 1] = v.y;
                b_reg[j + 2] = v.z; b_reg[j + 3] = v.w;
            }
            #pragma unroll
            for (int i = 0; i < TM; i++)
                #pragma unroll
                for (int j = 0; j < TN; j++)
                    acc[i][j] = fmaf(a_reg[i], b_reg[j], acc[i][j]);
        }
        __syncthreads();
    }

    // Epilogue: add bias, vectorized stores.
    #pragma unroll
    for (int i = 0; i < TM; i++) {
        const size_t row = (size_t)(bm + trow + i);
        #pragma unroll
        for (int j = 0; j < TN; j += 4) {
            const int col = bn + tcol + j;
            float4 o;
            o.x = acc[i][j + 0] + bias[col + 0];
            o.y = acc[i][j + 1] + bias[col + 1];
            o.z = acc[i][j + 2] + bias[col + 2];
            o.w = acc[i][j + 3] + bias[col + 3];
            *reinterpret_cast<float4*>(C + row * OUT_DIM + col) = o;
        }
    }
}

// ---------------------------------------------------------------------------
// Launch
// ---------------------------------------------------------------------------
extern "C" void kernel_launch(void* const* d_in, const int* in_sizes, int n_in,
                              void* d_out, int out_size)
{
    const float* x         = (const float*)d_in[0];      // [4,2048,4096]
    const float* centroids = (const float*)d_in[1];      // [256,8]
    const int*   labels    = (const int*)d_in[2];        // [2097152] (int32 in practice)
    const float* scale     = (const float*)d_in[3];      // [4096]
    const float* bias      = (const float*)d_in[4];      // [4096]
    float*       out       = (float*)d_out;              // [8192,4096]

    (void)in_sizes; (void)n_in; (void)out_size;

    // 1) decompress + fold scale into g_W
    decompress_kernel<<<(OUT_DIM * IN_DIM / CB_BLK) / 256, 256>>>(labels, centroids, scale);

    // 2) GEMM + bias
    dim3 grid(OUT_DIM / BN, M_DIM / BM);
    sgemm_kernel<<<grid, 256>>>(x, bias, out);
}

// round 4
// speedup vs baseline: 2.4934x; 2.4934x over previous
#include <cuda_runtime.h>
#include <cuda_bf16.h>
#include <cstdint>

#define OUT_DIM 4096
#define IN_DIM  4096
#define M_DIM   8192
#define CB_BLK  8

// ---- GEMM tiling ----
#define BM 128
#define BN 128
#define BK 32
#define NCHUNK (IN_DIM / BK)      // 128
#define PITCH  40                 // bf16 per smem row (32 data + 8 pad), 80B
#define TILEB  (128 * PITCH * 2)  // 10240 B per array per stage
#define SA_H 0
#define SA_L (TILEB)
#define SB_H (2 * TILEB)
#define SB_L (3 * TILEB)
#define STAGEB (4 * TILEB)        // 40960
#define NSTAGE 3
#define SMEM_TOTAL (NSTAGE * STAGEB)  // 122880

// bf16 hi/lo split scratch (static device arrays; allocation-guard safe)
__device__ __align__(16) __nv_bfloat16 g_Wh[(size_t)OUT_DIM * IN_DIM];
__device__ __align__(16) __nv_bfloat16 g_Wl[(size_t)OUT_DIM * IN_DIM];
__device__ __align__(16) __nv_bfloat16 g_xh[(size_t)M_DIM * IN_DIM];
__device__ __align__(16) __nv_bfloat16 g_xl[(size_t)M_DIM * IN_DIM];

// ---------------------------------------------------------------------------
// helpers
// ---------------------------------------------------------------------------
__device__ __forceinline__ uint32_t smem_u32(const void* p) {
    uint32_t a;
    asm("{ .reg .u64 t; cvta.to.shared.u64 t, %1; cvt.u32.u64 %0, t; }" : "=r"(a) : "l"(p));
    return a;
}
__device__ __forceinline__ void cp16(uint32_t saddr, const void* gaddr) {
    asm volatile("cp.async.cg.shared.global [%0], [%1], 16;" :: "r"(saddr), "l"(gaddr));
}
__device__ __forceinline__ void cp_commit() {
    asm volatile("cp.async.commit_group;" ::: "memory");
}
__device__ __forceinline__ void cp_wait1() {
    asm volatile("cp.async.wait_group 1;" ::: "memory");
}
__device__ __forceinline__ void ldm_x4(uint32_t* r, uint32_t addr) {
    asm volatile("ldmatrix.sync.aligned.m8n8.x4.shared.b16 {%0,%1,%2,%3}, [%4];"
                 : "=r"(r[0]), "=r"(r[1]), "=r"(r[2]), "=r"(r[3]) : "r"(addr));
}
__device__ __forceinline__ void mma16816(float* c, const uint32_t* a, const uint32_t* b) {
    asm volatile(
        "mma.sync.aligned.m16n8k16.row.col.f32.bf16.bf16.f32 "
        "{%0,%1,%2,%3}, {%4,%5,%6,%7}, {%8,%9}, {%0,%1,%2,%3};"
        : "+f"(c[0]), "+f"(c[1]), "+f"(c[2]), "+f"(c[3])
        : "r"(a[0]), "r"(a[1]), "r"(a[2]), "r"(a[3]), "r"(b[0]), "r"(b[1]));
}

// ---------------------------------------------------------------------------
// Prep 1: VQ decompress + fold scale + bf16 hi/lo split of W
// ---------------------------------------------------------------------------
__global__ void __launch_bounds__(256) decompress_split_kernel(
    const int* __restrict__ labels,
    const float* __restrict__ centroids,
    const float* __restrict__ scale)
{
    int j = blockIdx.x * blockDim.x + threadIdx.x;   // 0 .. 2097151
    int lab = labels[j] & 0xFF;
    const float4* c = reinterpret_cast<const float4*>(centroids + (size_t)lab * CB_BLK);
    float4 c0 = c[0], c1 = c[1];
    int k = (j * CB_BLK) & (IN_DIM - 1);
    const float4* s = reinterpret_cast<const float4*>(scale + k);
    float4 s0 = s[0], s1 = s[1];
    float w[8] = { c0.x * s0.x, c0.y * s0.y, c0.z * s0.z, c0.w * s0.w,
                   c1.x * s1.x, c1.y * s1.y, c1.z * s1.z, c1.w * s1.w };
    __align__(16) __nv_bfloat16 hi[8];
    __align__(16) __nv_bfloat16 lo[8];
    #pragma unroll
    for (int t = 0; t < 8; t++) {
        hi[t] = __float2bfloat16_rn(w[t]);
        lo[t] = __float2bfloat16_rn(w[t] - __bfloat162float(hi[t]));
    }
    *reinterpret_cast<uint4*>(&g_Wh[(size_t)j * CB_BLK]) = *reinterpret_cast<uint4*>(hi);
    *reinterpret_cast<uint4*>(&g_Wl[(size_t)j * CB_BLK]) = *reinterpret_cast<uint4*>(lo);
}

// ---------------------------------------------------------------------------
// Prep 2: split x into bf16 hi/lo
// ---------------------------------------------------------------------------
__global__ void __launch_bounds__(256) split_x_kernel(const float* __restrict__ x)
{
    size_t i = (size_t)blockIdx.x * blockDim.x + threadIdx.x;   // float4 index
    float4 v = reinterpret_cast<const float4*>(x)[i];
    float vv[4] = { v.x, v.y, v.z, v.w };
    __align__(8) __nv_bfloat16 hi[4];
    __align__(8) __nv_bfloat16 lo[4];
    #pragma unroll
    for (int t = 0; t < 4; t++) {
        hi[t] = __float2bfloat16_rn(vv[t]);
        lo[t] = __float2bfloat16_rn(vv[t] - __bfloat162float(hi[t]));
    }
    *reinterpret_cast<uint2*>(&g_xh[i * 4]) = *reinterpret_cast<uint2*>(hi);
    *reinterpret_cast<uint2*>(&g_xl[i * 4]) = *reinterpret_cast<uint2*>(lo);
}

// ---------------------------------------------------------------------------
// GEMM via mma.sync (HMMA): C = xh@Wh^T + xh@Wl^T + xl@Wh^T + bias
// 128x128 CTA tile, BK=32, 3-stage cp.async pipeline, 8 warps of 64x32.
// ---------------------------------------------------------------------------
__global__ void __launch_bounds__(256, 1) gemm_mma_kernel(
    const float* __restrict__ bias,
    float* __restrict__ C)
{
    extern __shared__ char smem[];
    const uint32_t sb = smem_u32(smem);
    const int tid  = threadIdx.x;
    const int wid  = tid >> 5;
    const int lane = tid & 31;
    const int bm = blockIdx.y * BM;
    const int bn = blockIdx.x * BN;
    const int warp_m = (wid >> 2) * 64;     // 0 or 64
    const int warp_n = (wid & 3) * 32;      // 0,32,64,96

    // per-thread load mapping (2 segments x 4 arrays per stage)
    const int r0 = tid >> 2;                // rows 0..63 (second: +64)
    const int sg = (tid & 3) << 3;          // k element offset 0,8,16,24

    float acc[4][4][4];
    #pragma unroll
    for (int m = 0; m < 4; m++)
        #pragma unroll
        for (int n = 0; n < 4; n++)
            #pragma unroll
            for (int v = 0; v < 4; v++) acc[m][n][v] = 0.0f;

    // issue one stage of cp.async loads
    auto issue = [&](int ch, int stg) {
        const int k0 = ch * BK;
        const uint32_t sbase = sb + stg * STAGEB;
        #pragma unroll
        for (int i = 0; i < 2; i++) {
            const int r = r0 + i * 64;
            const uint32_t so = (uint32_t)(r * (PITCH * 2) + sg * 2);
            const size_t gA = (size_t)(bm + r) * IN_DIM + k0 + sg;
            const size_t gB = (size_t)(bn + r) * IN_DIM + k0 + sg;
            cp16(sbase + SA_H + so, g_xh + gA);
            cp16(sbase + SA_L + so, g_xl + gA);
            cp16(sbase + SB_H + so, g_Wh + gB);
            cp16(sbase + SB_L + so, g_Wl + gB);
        }
    };

    issue(0, 0); cp_commit();
    issue(1, 1); cp_commit();

    // ldmatrix lane addressing (byte offsets within a tile)
    const uint32_t a_lane_off =
        (uint32_t)((warp_m + (lane & 15)) * (PITCH * 2) + (lane >> 4) * 16);
    const int b_n = warp_n + (lane & 7) + ((lane >> 4) << 3);
    const uint32_t b_lane_off =
        (uint32_t)(b_n * (PITCH * 2) + ((lane >> 3) & 1) * 16);

    for (int ch = 0; ch < NCHUNK; ch++) {
        const int stg = ch % NSTAGE;
        cp_wait1();
        __syncthreads();
        if (ch + 2 < NCHUNK) issue(ch + 2, (ch + 2) % NSTAGE);
        cp_commit();

        const uint32_t sbase = sb + stg * STAGEB;
        #pragma unroll
        for (int s16 = 0; s16 < 2; s16++) {
            const uint32_t kb = (uint32_t)(s16 * 32);   // 16 bf16 = 32B
            uint32_t ah[4][4], al[4][4];
            #pragma unroll
            for (int m = 0; m < 4; m++) {
                const uint32_t off = a_lane_off + (uint32_t)(m * 16 * PITCH * 2) + kb;
                ldm_x4(ah[m], sbase + SA_H + off);
                ldm_x4(al[m], sbase + SA_L + off);
            }
            uint32_t bh[4][2], bl[4][2];
            #pragma unroll
            for (int np = 0; np < 2; np++) {
                const uint32_t off = b_lane_off + (uint32_t)(np * 16 * PITCH * 2) + kb;
                uint32_t th[4], tl[4];
                ldm_x4(th, sbase + SB_H + off);
                ldm_x4(tl, sbase + SB_L + off);
                bh[np * 2][0] = th[0]; bh[np * 2][1] = th[1];
                bh[np * 2 + 1][0] = th[2]; bh[np * 2 + 1][1] = th[3];
                bl[np * 2][0] = tl[0]; bl[np * 2][1] = tl[1];
                bl[np * 2 + 1][0] = tl[2]; bl[np * 2 + 1][1] = tl[3];
            }
            #pragma unroll
            for (int m = 0; m < 4; m++)
                #pragma unroll
                for (int n = 0; n < 4; n++) {
                    mma16816(acc[m][n], ah[m], bh[n]);
                    mma16816(acc[m][n], ah[m], bl[n]);
                    mma16816(acc[m][n], al[m], bh[n]);
                }
        }
        __syncthreads();
    }

    // Epilogue: add bias, store fp32.
    const int erow = lane >> 2;
    const int ecol = (lane & 3) * 2;
    #pragma unroll
    for (int m = 0; m < 4; m++) {
        const size_t row = (size_t)(bm + warp_m + m * 16 + erow);
        #pragma unroll
        for (int n = 0; n < 4; n++) {
            const int col = bn + warp_n + n * 8 + ecol;
            const float bx = bias[col], by = bias[col + 1];
            float2 o0 = make_float2(acc[m][n][0] + bx, acc[m][n][1] + by);
            float2 o1 = make_float2(acc[m][n][2] + bx, acc[m][n][3] + by);
            *reinterpret_cast<float2*>(C + row * OUT_DIM + col) = o0;
            *reinterpret_cast<float2*>(C + (row + 8) * OUT_DIM + col) = o1;
        }
    }
}

// ---------------------------------------------------------------------------
// Launch
// ---------------------------------------------------------------------------
extern "C" void kernel_launch(void* const* d_in, const int* in_sizes, int n_in,
                              void* d_out, int out_size)
{
    const float* x         = (const float*)d_in[0];      // [4,2048,4096]
    const float* centroids = (const float*)d_in[1];      // [256,8]
    const int*   labels    = (const int*)d_in[2];        // [2097152] int32
    const float* scale     = (const float*)d_in[3];      // [4096]
    const float* bias      = (const float*)d_in[4];      // [4096]
    float*       out       = (float*)d_out;              // [8192,4096]

    (void)in_sizes; (void)n_in; (void)out_size;

    cudaFuncSetAttribute(gemm_mma_kernel,
                         cudaFuncAttributeMaxDynamicSharedMemorySize, SMEM_TOTAL);

    decompress_split_kernel<<<(OUT_DIM * IN_DIM / CB_BLK) / 256, 256>>>(labels, centroids, scale);
    split_x_kernel<<<(int)(((size_t)M_DIM * IN_DIM / 4) / 256), 256>>>(x);

    dim3 grid(OUT_DIM / BN, M_DIM / BM);   // (32, 64)
    gemm_mma_kernel<<<grid, 256, SMEM_TOTAL>>>(bias, out);
}

// round 5
// speedup vs baseline: 2.9116x; 1.1677x over previous
#include <cuda_runtime.h>
#include <cuda_bf16.h>
#include <cstdint>

#define OUT_DIM 4096
#define IN_DIM  4096
#define M_DIM   8192
#define CB_BLK  8

// ---- GEMM tiling ----
#define BM 128
#define BN 128
#define BK 64
#define NCHUNK (IN_DIM / BK)      // 64
#define PITCHB 144                // bytes per smem row (128 data + 16 pad)
#define TILEB  (128 * PITCHB)     // 18432 B per array per stage
#define SA_H 0
#define SA_L (TILEB)
#define SB_H (2 * TILEB)
#define SB_L (3 * TILEB)
#define STAGEB (4 * TILEB)        // 73728
#define NSTAGE 2
#define SMEM_TOTAL (NSTAGE * STAGEB)  // 147456

// bf16 hi/lo split scratch (static device arrays; allocation-guard safe)
__device__ __align__(16) __nv_bfloat16 g_Wh[(size_t)OUT_DIM * IN_DIM];
__device__ __align__(16) __nv_bfloat16 g_Wl[(size_t)OUT_DIM * IN_DIM];
__device__ __align__(16) __nv_bfloat16 g_xh[(size_t)M_DIM * IN_DIM];
__device__ __align__(16) __nv_bfloat16 g_xl[(size_t)M_DIM * IN_DIM];

// ---------------------------------------------------------------------------
// helpers
// ---------------------------------------------------------------------------
__device__ __forceinline__ uint32_t smem_u32(const void* p) {
    uint32_t a;
    asm("{ .reg .u64 t; cvta.to.shared.u64 t, %1; cvt.u32.u64 %0, t; }" : "=r"(a) : "l"(p));
    return a;
}
__device__ __forceinline__ void cp16(uint32_t saddr, const void* gaddr) {
    asm volatile("cp.async.cg.shared.global [%0], [%1], 16;" :: "r"(saddr), "l"(gaddr));
}
__device__ __forceinline__ void cp_commit() {
    asm volatile("cp.async.commit_group;" ::: "memory");
}
__device__ __forceinline__ void cp_wait0() {
    asm volatile("cp.async.wait_group 0;" ::: "memory");
}
__device__ __forceinline__ void ldm_x4(uint32_t* r, uint32_t addr) {
    asm volatile("ldmatrix.sync.aligned.m8n8.x4.shared.b16 {%0,%1,%2,%3}, [%4];"
                 : "=r"(r[0]), "=r"(r[1]), "=r"(r[2]), "=r"(r[3]) : "r"(addr));
}
__device__ __forceinline__ void mma16816(float* c, const uint32_t* a, const uint32_t* b) {
    asm volatile(
        "mma.sync.aligned.m16n8k16.row.col.f32.bf16.bf16.f32 "
        "{%0,%1,%2,%3}, {%4,%5,%6,%7}, {%8,%9}, {%0,%1,%2,%3};"
        : "+f"(c[0]), "+f"(c[1]), "+f"(c[2]), "+f"(c[3])
        : "r"(a[0]), "r"(a[1]), "r"(a[2]), "r"(a[3]), "r"(b[0]), "r"(b[1]));
}

// ---------------------------------------------------------------------------
// Prep 1: VQ decompress + fold scale + bf16 hi/lo split of W
// ---------------------------------------------------------------------------
__global__ void __launch_bounds__(256) decompress_split_kernel(
    const int* __restrict__ labels,
    const float* __restrict__ centroids,
    const float* __restrict__ scale)
{
    int j = blockIdx.x * blockDim.x + threadIdx.x;   // 0 .. 2097151
    int lab = labels[j] & 0xFF;
    const float4* c = reinterpret_cast<const float4*>(centroids + (size_t)lab * CB_BLK);
    float4 c0 = c[0], c1 = c[1];
    int k = (j * CB_BLK) & (IN_DIM - 1);
    const float4* s = reinterpret_cast<const float4*>(scale + k);
    float4 s0 = s[0], s1 = s[1];
    float w[8] = { c0.x * s0.x, c0.y * s0.y, c0.z * s0.z, c0.w * s0.w,
                   c1.x * s1.x, c1.y * s1.y, c1.z * s1.z, c1.w * s1.w };
    __align__(16) __nv_bfloat16 hi[8];
    __align__(16) __nv_bfloat16 lo[8];
    #pragma unroll
    for (int t = 0; t < 8; t++) {
        hi[t] = __float2bfloat16_rn(w[t]);
        lo[t] = __float2bfloat16_rn(w[t] - __bfloat162float(hi[t]));
    }
    *reinterpret_cast<uint4*>(&g_Wh[(size_t)j * CB_BLK]) = *reinterpret_cast<uint4*>(hi);
    *reinterpret_cast<uint4*>(&g_Wl[(size_t)j * CB_BLK]) = *reinterpret_cast<uint4*>(lo);
}

// ---------------------------------------------------------------------------
// Prep 2: split x into bf16 hi/lo
// ---------------------------------------------------------------------------
__global__ void __launch_bounds__(256) split_x_kernel(const float* __restrict__ x)
{
    size_t i = (size_t)blockIdx.x * blockDim.x + threadIdx.x;   // float4 index
    float4 v = reinterpret_cast<const float4*>(x)[i];
    float vv[4] = { v.x, v.y, v.z, v.w };
    __align__(8) __nv_bfloat16 hi[4];
    __align__(8) __nv_bfloat16 lo[4];
    #pragma unroll
    for (int t = 0; t < 4; t++) {
        hi[t] = __float2bfloat16_rn(vv[t]);
        lo[t] = __float2bfloat16_rn(vv[t] - __bfloat162float(hi[t]));
    }
    *reinterpret_cast<uint2*>(&g_xh[i * 4]) = *reinterpret_cast<uint2*>(hi);
    *reinterpret_cast<uint2*>(&g_xl[i * 4]) = *reinterpret_cast<uint2*>(lo);
}

// ---------------------------------------------------------------------------
// GEMM via mma.sync (HMMA): C = xh@Wh^T + xh@Wl^T + xl@Wh^T + bias
// 128x128 CTA tile, BK=64, 2-stage cp.async pipeline, ONE barrier per chunk,
// 8 warps of 64x32.
// ---------------------------------------------------------------------------
__global__ void __launch_bounds__(256, 1) gemm_mma_kernel(
    const float* __restrict__ bias,
    float* __restrict__ C)
{
    extern __shared__ char smem[];
    const uint32_t sb = smem_u32(smem);
    const int tid  = threadIdx.x;
    const int wid  = tid >> 5;
    const int lane = tid & 31;
    const int bm = blockIdx.y * BM;
    const int bn = blockIdx.x * BN;
    const int warp_m = (wid >> 2) * 64;     // 0 or 64
    const int warp_n = (wid & 3) * 32;      // 0,32,64,96

    float acc[4][4][4];
    #pragma unroll
    for (int m = 0; m < 4; m++)
        #pragma unroll
        for (int n = 0; n < 4; n++)
            #pragma unroll
            for (int v = 0; v < 4; v++) acc[m][n][v] = 0.0f;

    // one stage = 128 rows x 128B for each of 4 arrays; 16 cp16 per thread
    auto issue = [&](int ch, int stg) {
        const int k0 = ch * BK;
        const uint32_t sbase = sb + stg * STAGEB;
        #pragma unroll
        for (int i = 0; i < 4; i++) {
            const int u = tid + i * 256;
            const int r = u >> 3;              // 0..127
            const int c = u & 7;               // 16B segment 0..7
            const uint32_t so = (uint32_t)(r * PITCHB + c * 16);
            const size_t gA = (size_t)(bm + r) * IN_DIM + k0 + c * 8;
            const size_t gB = (size_t)(bn + r) * IN_DIM + k0 + c * 8;
            cp16(sbase + SA_H + so, g_xh + gA);
            cp16(sbase + SA_L + so, g_xl + gA);
            cp16(sbase + SB_H + so, g_Wh + gB);
            cp16(sbase + SB_L + so, g_Wl + gB);
        }
    };

    issue(0, 0);
    cp_commit();

    // ldmatrix lane addressing (byte offsets within a tile)
    const uint32_t a_lane_off =
        (uint32_t)((warp_m + (lane & 15)) * PITCHB + (lane >> 4) * 16);
    const int b_n = warp_n + (lane & 7) + ((lane >> 4) << 3);
    const uint32_t b_lane_off =
        (uint32_t)(b_n * PITCHB + ((lane >> 3) & 1) * 16);

    for (int ch = 0; ch < NCHUNK; ch++) {
        cp_wait0();
        __syncthreads();            // single barrier per chunk
        if (ch + 1 < NCHUNK) issue(ch + 1, (ch + 1) & 1);
        cp_commit();

        const uint32_t sbase = sb + (ch & 1) * STAGEB;
        #pragma unroll
        for (int s16 = 0; s16 < 4; s16++) {
            const uint32_t kb = (uint32_t)(s16 * 32);   // 16 bf16 = 32B
            uint32_t ah[4][4], al[4][4];
            #pragma unroll
            for (int m = 0; m < 4; m++) {
                const uint32_t off = a_lane_off + (uint32_t)(m * 16 * PITCHB) + kb;
                ldm_x4(ah[m], sbase + SA_H + off);
                ldm_x4(al[m], sbase + SA_L + off);
            }
            uint32_t bh[4][2], bl[4][2];
            #pragma unroll
            for (int np = 0; np < 2; np++) {
                const uint32_t off = b_lane_off + (uint32_t)(np * 16 * PITCHB) + kb;
                uint32_t th[4], tl[4];
                ldm_x4(th, sbase + SB_H + off);
                ldm_x4(tl, sbase + SB_L + off);
                bh[np * 2][0] = th[0]; bh[np * 2][1] = th[1];
                bh[np * 2 + 1][0] = th[2]; bh[np * 2 + 1][1] = th[3];
                bl[np * 2][0] = tl[0]; bl[np * 2][1] = tl[1];
                bl[np * 2 + 1][0] = tl[2]; bl[np * 2 + 1][1] = tl[3];
            }
            #pragma unroll
            for (int m = 0; m < 4; m++)
                #pragma unroll
                for (int n = 0; n < 4; n++) {
                    mma16816(acc[m][n], ah[m], bh[n]);
                    mma16816(acc[m][n], ah[m], bl[n]);
                    mma16816(acc[m][n], al[m], bh[n]);
                }
        }
    }

    // Epilogue: add bias, store fp32.
    const int erow = lane >> 2;
    const int ecol = (lane & 3) * 2;
    #pragma unroll
    for (int m = 0; m < 4; m++) {
        const size_t row = (size_t)(bm + warp_m + m * 16 + erow);
        #pragma unroll
        for (int n = 0; n < 4; n++) {
            const int col = bn + warp_n + n * 8 + ecol;
            const float bx = bias[col], by = bias[col + 1];
            float2 o0 = make_float2(acc[m][n][0] + bx, acc[m][n][1] + by);
            float2 o1 = make_float2(acc[m][n][2] + bx, acc[m][n][3] + by);
            *reinterpret_cast<float2*>(C + row * OUT_DIM + col) = o0;
            *reinterpret_cast<float2*>(C + (row + 8) * OUT_DIM + col) = o1;
        }
    }
}

// ---------------------------------------------------------------------------
// Launch
// ---------------------------------------------------------------------------
extern "C" void kernel_launch(void* const* d_in, const int* in_sizes, int n_in,
                              void* d_out, int out_size)
{
    const float* x         = (const float*)d_in[0];      // [4,2048,4096]
    const float* centroids = (const float*)d_in[1];      // [256,8]
    const int*   labels    = (const int*)d_in[2];        // [2097152] int32
    const float* scale     = (const float*)d_in[3];      // [4096]
    const float* bias      = (const float*)d_in[4];      // [4096]
    float*       out       = (float*)d_out;              // [8192,4096]

    (void)in_sizes; (void)n_in; (void)out_size;

    cudaFuncSetAttribute(gemm_mma_kernel,
                         cudaFuncAttributeMaxDynamicSharedMemorySize, SMEM_TOTAL);

    decompress_split_kernel<<<(OUT_DIM * IN_DIM / CB_BLK) / 256, 256>>>(labels, centroids, scale);
    split_x_kernel<<<(int)(((size_t)M_DIM * IN_DIM / 4) / 256), 256>>>(x);

    dim3 grid(OUT_DIM / BN, M_DIM / BM);   // (32, 64)
    gemm_mma_kernel<<<grid, 256, SMEM_TOTAL>>>(bias, out);
}

// round 6
// speedup vs baseline: 2.9143x; 1.0009x over previous
#include <cuda_runtime.h>
#include <cuda_bf16.h>
#include <cstdint>

#define OUT_DIM 4096
#define IN_DIM  4096
#define M_DIM   8192
#define CB_BLK  8

// ---- GEMM tiling ----
#define BM 128
#define BN 128
#define BK 64
#define NCHUNK (IN_DIM / BK)      // 64
#define PITCHB 144                // bytes per smem row (128 data + 16 pad)
#define TILEB  (128 * PITCHB)     // 18432 B per array per stage
#define SA_H 0
#define SA_L (TILEB)
#define SB_H (2 * TILEB)
#define SB_L (3 * TILEB)
#define STAGEB (4 * TILEB)        // 73728
#define NSTAGE 3
#define SMEM_TOTAL (NSTAGE * STAGEB)  // 221184 (216 KB, fits 227 KB CTA limit)

// bf16 hi/lo split scratch (static device arrays; allocation-guard safe)
__device__ __align__(16) __nv_bfloat16 g_Wh[(size_t)OUT_DIM * IN_DIM];
__device__ __align__(16) __nv_bfloat16 g_Wl[(size_t)OUT_DIM * IN_DIM];
__device__ __align__(16) __nv_bfloat16 g_xh[(size_t)M_DIM * IN_DIM];
__device__ __align__(16) __nv_bfloat16 g_xl[(size_t)M_DIM * IN_DIM];

// ---------------------------------------------------------------------------
// helpers
// ---------------------------------------------------------------------------
__device__ __forceinline__ uint32_t smem_u32(const void* p) {
    uint32_t a;
    asm("{ .reg .u64 t; cvta.to.shared.u64 t, %1; cvt.u32.u64 %0, t; }" : "=r"(a) : "l"(p));
    return a;
}
__device__ __forceinline__ void cp16(uint32_t saddr, const void* gaddr) {
    asm volatile("cp.async.cg.shared.global [%0], [%1], 16;" :: "r"(saddr), "l"(gaddr));
}
__device__ __forceinline__ void cp_commit() {
    asm volatile("cp.async.commit_group;" ::: "memory");
}
__device__ __forceinline__ void cp_wait1() {
    asm volatile("cp.async.wait_group 1;" ::: "memory");
}
__device__ __forceinline__ void ldm_x4(uint32_t* r, uint32_t addr) {
    asm volatile("ldmatrix.sync.aligned.m8n8.x4.shared.b16 {%0,%1,%2,%3}, [%4];"
                 : "=r"(r[0]), "=r"(r[1]), "=r"(r[2]), "=r"(r[3]) : "r"(addr));
}
__device__ __forceinline__ void mma16816(float* c, const uint32_t* a, const uint32_t* b) {
    asm volatile(
        "mma.sync.aligned.m16n8k16.row.col.f32.bf16.bf16.f32 "
        "{%0,%1,%2,%3}, {%4,%5,%6,%7}, {%8,%9}, {%0,%1,%2,%3};"
        : "+f"(c[0]), "+f"(c[1]), "+f"(c[2]), "+f"(c[3])
        : "r"(a[0]), "r"(a[1]), "r"(a[2]), "r"(a[3]), "r"(b[0]), "r"(b[1]));
}

// ---------------------------------------------------------------------------
// Prep 1: VQ decompress + fold scale + bf16 hi/lo split of W
// ---------------------------------------------------------------------------
__global__ void __launch_bounds__(256) decompress_split_kernel(
    const int* __restrict__ labels,
    const float* __restrict__ centroids,
    const float* __restrict__ scale)
{
    int j = blockIdx.x * blockDim.x + threadIdx.x;   // 0 .. 2097151
    int lab = labels[j] & 0xFF;
    const float4* c = reinterpret_cast<const float4*>(centroids + (size_t)lab * CB_BLK);
    float4 c0 = c[0], c1 = c[1];
    int k = (j * CB_BLK) & (IN_DIM - 1);
    const float4* s = reinterpret_cast<const float4*>(scale + k);
    float4 s0 = s[0], s1 = s[1];
    float w[8] = { c0.x * s0.x, c0.y * s0.y, c0.z * s0.z, c0.w * s0.w,
                   c1.x * s1.x, c1.y * s1.y, c1.z * s1.z, c1.w * s1.w };
    __align__(16) __nv_bfloat16 hi[8];
    __align__(16) __nv_bfloat16 lo[8];
    #pragma unroll
    for (int t = 0; t < 8; t++) {
        hi[t] = __float2bfloat16_rn(w[t]);
        lo[t] = __float2bfloat16_rn(w[t] - __bfloat162float(hi[t]));
    }
    *reinterpret_cast<uint4*>(&g_Wh[(size_t)j * CB_BLK]) = *reinterpret_cast<uint4*>(hi);
    *reinterpret_cast<uint4*>(&g_Wl[(size_t)j * CB_BLK]) = *reinterpret_cast<uint4*>(lo);
}

// ---------------------------------------------------------------------------
// Prep 2: split x into bf16 hi/lo
// ---------------------------------------------------------------------------
__global__ void __launch_bounds__(256) split_x_kernel(const float* __restrict__ x)
{
    size_t i = (size_t)blockIdx.x * blockDim.x + threadIdx.x;   // float4 index
    float4 v = reinterpret_cast<const float4*>(x)[i];
    float vv[4] = { v.x, v.y, v.z, v.w };
    __align__(8) __nv_bfloat16 hi[4];
    __align__(8) __nv_bfloat16 lo[4];
    #pragma unroll
    for (int t = 0; t < 4; t++) {
        hi[t] = __float2bfloat16_rn(vv[t]);
        lo[t] = __float2bfloat16_rn(vv[t] - __bfloat162float(hi[t]));
    }
    *reinterpret_cast<uint2*>(&g_xh[i * 4]) = *reinterpret_cast<uint2*>(hi);
    *reinterpret_cast<uint2*>(&g_xl[i * 4]) = *reinterpret_cast<uint2*>(lo);
}

// ---------------------------------------------------------------------------
// GEMM via mma.sync (HMMA): C = xh@Wh^T + xh@Wl^T + xl@Wh^T + bias
// 128x128 CTA tile, BK=64, 3-stage cp.async pipeline (wait_group 1 -> each
// chunk's loads get ~2 compute-chunks of slack), one barrier per chunk,
// 8 warps of 64x32.
// ---------------------------------------------------------------------------
__global__ void __launch_bounds__(256, 1) gemm_mma_kernel(
    const float* __restrict__ bias,
    float* __restrict__ C)
{
    extern __shared__ char smem[];
    const uint32_t sb = smem_u32(smem);
    const int tid  = threadIdx.x;
    const int wid  = tid >> 5;
    const int lane = tid & 31;
    const int bm = blockIdx.y * BM;
    const int bn = blockIdx.x * BN;
    const int warp_m = (wid >> 2) * 64;     // 0 or 64
    const int warp_n = (wid & 3) * 32;      // 0,32,64,96

    float acc[4][4][4];
    #pragma unroll
    for (int m = 0; m < 4; m++)
        #pragma unroll
        for (int n = 0; n < 4; n++)
            #pragma unroll
            for (int v = 0; v < 4; v++) acc[m][n][v] = 0.0f;

    // one stage = 128 rows x 128B for each of 4 arrays; 16 cp16 per thread
    auto issue = [&](int ch, int stg) {
        const int k0 = ch * BK;
        const uint32_t sbase = sb + stg * STAGEB;
        #pragma unroll
        for (int i = 0; i < 4; i++) {
            const int u = tid + i * 256;
            const int r = u >> 3;              // 0..127
            const int c = u & 7;               // 16B segment 0..7
            const uint32_t so = (uint32_t)(r * PITCHB + c * 16);
            const size_t gA = (size_t)(bm + r) * IN_DIM + k0 + c * 8;
            const size_t gB = (size_t)(bn + r) * IN_DIM + k0 + c * 8;
            cp16(sbase + SA_H + so, g_xh + gA);
            cp16(sbase + SA_L + so, g_xl + gA);
            cp16(sbase + SB_H + so, g_Wh + gB);
            cp16(sbase + SB_L + so, g_Wl + gB);
        }
    };

    issue(0, 0); cp_commit();
    issue(1, 1); cp_commit();

    // ldmatrix lane addressing (byte offsets within a tile)
    const uint32_t a_lane_off =
        (uint32_t)((warp_m + (lane & 15)) * PITCHB + (lane >> 4) * 16);
    const int b_n = warp_n + (lane & 7) + ((lane >> 4) << 3);
    const uint32_t b_lane_off =
        (uint32_t)(b_n * PITCHB + ((lane >> 3) & 1) * 16);

    int stg = 0;
    for (int ch = 0; ch < NCHUNK; ch++) {
        cp_wait1();                 // chunk ch resident; ch+1 may still be in flight
        __syncthreads();            // single barrier per chunk
        if (ch + 2 < NCHUNK) {
            int nstg = stg + 2; if (nstg >= NSTAGE) nstg -= NSTAGE;
            issue(ch + 2, nstg);
        }
        cp_commit();

        const uint32_t sbase = sb + stg * STAGEB;
        #pragma unroll
        for (int s16 = 0; s16 < 4; s16++) {
            const uint32_t kb = (uint32_t)(s16 * 32);   // 16 bf16 = 32B
            uint32_t ah[4][4], al[4][4];
            #pragma unroll
            for (int m = 0; m < 4; m++) {
                const uint32_t off = a_lane_off + (uint32_t)(m * 16 * PITCHB) + kb;
                ldm_x4(ah[m], sbase + SA_H + off);
                ldm_x4(al[m], sbase + SA_L + off);
            }
            uint32_t bh[4][2], bl[4][2];
            #pragma unroll
            for (int np = 0; np < 2; np++) {
                const uint32_t off = b_lane_off + (uint32_t)(np * 16 * PITCHB) + kb;
                uint32_t th[4], tl[4];
                ldm_x4(th, sbase + SB_H + off);
                ldm_x4(tl, sbase + SB_L + off);
                bh[np * 2][0] = th[0]; bh[np * 2][1] = th[1];
                bh[np * 2 + 1][0] = th[2]; bh[np * 2 + 1][1] = th[3];
                bl[np * 2][0] = tl[0]; bl[np * 2][1] = tl[1];
                bl[np * 2 + 1][0] = tl[2]; bl[np * 2 + 1][1] = tl[3];
            }
            #pragma unroll
            for (int m = 0; m < 4; m++)
                #pragma unroll
                for (int n = 0; n < 4; n++) {
                    mma16816(acc[m][n], ah[m], bh[n]);
                    mma16816(acc[m][n], ah[m], bl[n]);
                    mma16816(acc[m][n], al[m], bh[n]);
                }
        }
        if (++stg == NSTAGE) stg = 0;
    }

    // Epilogue: add bias, store fp32.
    const int erow = lane >> 2;
    const int ecol = (lane & 3) * 2;
    #pragma unroll
    for (int m = 0; m < 4; m++) {
        const size_t row = (size_t)(bm + warp_m + m * 16 + erow);
        #pragma unroll
        for (int n = 0; n < 4; n++) {
            const int col = bn + warp_n + n * 8 + ecol;
            const float bx = bias[col], by = bias[col + 1];
            float2 o0 = make_float2(acc[m][n][0] + bx, acc[m][n][1] + by);
            float2 o1 = make_float2(acc[m][n][2] + bx, acc[m][n][3] + by);
            *reinterpret_cast<float2*>(C + row * OUT_DIM + col) = o0;
            *reinterpret_cast<float2*>(C + (row + 8) * OUT_DIM + col) = o1;
        }
    }
}

// ---------------------------------------------------------------------------
// Launch
// ---------------------------------------------------------------------------
extern "C" void kernel_launch(void* const* d_in, const int* in_sizes, int n_in,
                              void* d_out, int out_size)
{
    const float* x         = (const float*)d_in[0];      // [4,2048,4096]
    const float* centroids = (const float*)d_in[1];      // [256,8]
    const int*   labels    = (const int*)d_in[2];        // [2097152] int32
    const float* scale     = (const float*)d_in[3];      // [4096]
    const float* bias      = (const float*)d_in[4];      // [4096]
    float*       out       = (float*)d_out;              // [8192,4096]

    (void)in_sizes; (void)n_in; (void)out_size;

    cudaFuncSetAttribute(gemm_mma_kernel,
                         cudaFuncAttributeMaxDynamicSharedMemorySize, SMEM_TOTAL);

    decompress_split_kernel<<<(OUT_DIM * IN_DIM / CB_BLK) / 256, 256>>>(labels, centroids, scale);
    split_x_kernel<<<(int)(((size_t)M_DIM * IN_DIM / 4) / 256), 256>>>(x);

    dim3 grid(OUT_DIM / BN, M_DIM / BM);   // (32, 64)
    gemm_mma_kernel<<<grid, 256, SMEM_TOTAL>>>(bias, out);
}

// round 7
// speedup vs baseline: 3.1317x; 1.0746x over previous
#include <cuda_runtime.h>
#include <cuda_bf16.h>
#include <cstdint>

#define OUT_DIM 4096
#define IN_DIM  4096
#define M_DIM   8192
#define CB_BLK  8

// ---- GEMM tiling ----
#define BM 128
#define BN 256
#define BK 64
#define NCHUNK (IN_DIM / BK)      // 64
#define PITCHB 144                // bytes per smem row (128 data + 16 pad)
#define ATILE  (128 * PITCHB)     // 18432
#define BTILE  (256 * PITCHB)     // 36864
#define SA_H 0
#define SA_L (ATILE)
#define SB_H (2 * ATILE)
#define SB_L (2 * ATILE + BTILE)
#define STAGEB (2 * ATILE + 2 * BTILE)   // 110592
#define NSTAGE 2
#define SMEM_TOTAL (NSTAGE * STAGEB)     // 221184 (216 KB)

// bf16 hi/lo split scratch (static device arrays; allocation-guard safe)
__device__ __align__(16) __nv_bfloat16 g_Wh[(size_t)OUT_DIM * IN_DIM];
__device__ __align__(16) __nv_bfloat16 g_Wl[(size_t)OUT_DIM * IN_DIM];
__device__ __align__(16) __nv_bfloat16 g_xh[(size_t)M_DIM * IN_DIM];
__device__ __align__(16) __nv_bfloat16 g_xl[(size_t)M_DIM * IN_DIM];

// ---------------------------------------------------------------------------
// helpers
// ---------------------------------------------------------------------------
__device__ __forceinline__ uint32_t smem_u32(const void* p) {
    uint32_t a;
    asm("{ .reg .u64 t; cvta.to.shared.u64 t, %1; cvt.u32.u64 %0, t; }" : "=r"(a) : "l"(p));
    return a;
}
__device__ __forceinline__ void cp16(uint32_t saddr, const void* gaddr) {
    asm volatile("cp.async.cg.shared.global [%0], [%1], 16;" :: "r"(saddr), "l"(gaddr));
}
__device__ __forceinline__ void cp_commit() {
    asm volatile("cp.async.commit_group;" ::: "memory");
}
__device__ __forceinline__ void cp_wait0() {
    asm volatile("cp.async.wait_group 0;" ::: "memory");
}
__device__ __forceinline__ void ldm_x4(uint32_t* r, uint32_t addr) {
    asm volatile("ldmatrix.sync.aligned.m8n8.x4.shared.b16 {%0,%1,%2,%3}, [%4];"
                 : "=r"(r[0]), "=r"(r[1]), "=r"(r[2]), "=r"(r[3]) : "r"(addr));
}
__device__ __forceinline__ void mma16816(float* c, const uint32_t* a, const uint32_t* b) {
    asm volatile(
        "mma.sync.aligned.m16n8k16.row.col.f32.bf16.bf16.f32 "
        "{%0,%1,%2,%3}, {%4,%5,%6,%7}, {%8,%9}, {%0,%1,%2,%3};"
        : "+f"(c[0]), "+f"(c[1]), "+f"(c[2]), "+f"(c[3])
        : "r"(a[0]), "r"(a[1]), "r"(a[2]), "r"(a[3]), "r"(b[0]), "r"(b[1]));
}

// ---------------------------------------------------------------------------
// Prep 1: VQ decompress + fold scale + bf16 hi/lo split of W
// ---------------------------------------------------------------------------
__global__ void __launch_bounds__(256) decompress_split_kernel(
    const int* __restrict__ labels,
    const float* __restrict__ centroids,
    const float* __restrict__ scale)
{
    int j = blockIdx.x * blockDim.x + threadIdx.x;   // 0 .. 2097151
    int lab = labels[j] & 0xFF;
    const float4* c = reinterpret_cast<const float4*>(centroids + (size_t)lab * CB_BLK);
    float4 c0 = c[0], c1 = c[1];
    int k = (j * CB_BLK) & (IN_DIM - 1);
    const float4* s = reinterpret_cast<const float4*>(scale + k);
    float4 s0 = s[0], s1 = s[1];
    float w[8] = { c0.x * s0.x, c0.y * s0.y, c0.z * s0.z, c0.w * s0.w,
                   c1.x * s1.x, c1.y * s1.y, c1.z * s1.z, c1.w * s1.w };
    __align__(16) __nv_bfloat16 hi[8];
    __align__(16) __nv_bfloat16 lo[8];
    #pragma unroll
    for (int t = 0; t < 8; t++) {
        hi[t] = __float2bfloat16_rn(w[t]);
        lo[t] = __float2bfloat16_rn(w[t] - __bfloat162float(hi[t]));
    }
    *reinterpret_cast<uint4*>(&g_Wh[(size_t)j * CB_BLK]) = *reinterpret_cast<uint4*>(hi);
    *reinterpret_cast<uint4*>(&g_Wl[(size_t)j * CB_BLK]) = *reinterpret_cast<uint4*>(lo);
}

// ---------------------------------------------------------------------------
// Prep 2: split x into bf16 hi/lo
// ---------------------------------------------------------------------------
__global__ void __launch_bounds__(256) split_x_kernel(const float* __restrict__ x)
{
    size_t i = (size_t)blockIdx.x * blockDim.x + threadIdx.x;   // float4 index
    float4 v = reinterpret_cast<const float4*>(x)[i];
    float vv[4] = { v.x, v.y, v.z, v.w };
    __align__(8) __nv_bfloat16 hi[4];
    __align__(8) __nv_bfloat16 lo[4];
    #pragma unroll
    for (int t = 0; t < 4; t++) {
        hi[t] = __float2bfloat16_rn(vv[t]);
        lo[t] = __float2bfloat16_rn(vv[t] - __bfloat162float(hi[t]));
    }
    *reinterpret_cast<uint2*>(&g_xh[i * 4]) = *reinterpret_cast<uint2*>(hi);
    *reinterpret_cast<uint2*>(&g_xl[i * 4]) = *reinterpret_cast<uint2*>(lo);
}

// ---------------------------------------------------------------------------
// GEMM via mma.sync (HMMA): C = xh@Wh^T + xh@Wl^T + xl@Wh^T + bias
// 128x256 CTA tile, BK=64, 2-stage cp.async pipeline, one barrier per chunk,
// 8 warps of 64x64 (2x4 warp grid) -> 1.5x less smem-read traffic per MAC.
// ---------------------------------------------------------------------------
__global__ void __launch_bounds__(256, 1) gemm_mma_kernel(
    const float* __restrict__ bias,
    float* __restrict__ C)
{
    extern __shared__ char smem[];
    const uint32_t sb = smem_u32(smem);
    const int tid  = threadIdx.x;
    const int wid  = tid >> 5;
    const int lane = tid & 31;
    const int bm = blockIdx.y * BM;
    const int bn = blockIdx.x * BN;
    const int warp_m = (wid >> 2) * 64;     // 0 or 64
    const int warp_n = (wid & 3) * 64;      // 0,64,128,192

    float acc[4][8][4];
    #pragma unroll
    for (int m = 0; m < 4; m++)
        #pragma unroll
        for (int n = 0; n < 8; n++)
            #pragma unroll
            for (int v = 0; v < 4; v++) acc[m][n][v] = 0.0f;

    // one stage: A 128 rows + B 256 rows, 128B/row, hi+lo; 24 cp16 per thread
    auto issue = [&](int ch, int stg) {
        const int k0 = ch * BK;
        const uint32_t sbase = sb + stg * STAGEB;
        #pragma unroll
        for (int i = 0; i < 4; i++) {
            const int u = tid + i * 256;
            const int r = u >> 3;              // 0..127
            const int c = u & 7;
            const uint32_t so = (uint32_t)(r * PITCHB + c * 16);
            const size_t gA = (size_t)(bm + r) * IN_DIM + k0 + c * 8;
            cp16(sbase + SA_H + so, g_xh + gA);
            cp16(sbase + SA_L + so, g_xl + gA);
        }
        #pragma unroll
        for (int i = 0; i < 8; i++) {
            const int u = tid + i * 256;
            const int r = u >> 3;              // 0..255
            const int c = u & 7;
            const uint32_t so = (uint32_t)(r * PITCHB + c * 16);
            const size_t gB = (size_t)(bn + r) * IN_DIM + k0 + c * 8;
            cp16(sbase + SB_H + so, g_Wh + gB);
            cp16(sbase + SB_L + so, g_Wl + gB);
        }
    };

    issue(0, 0);
    cp_commit();

    // ldmatrix lane addressing (byte offsets within a tile)
    const uint32_t a_lane_off =
        (uint32_t)((warp_m + (lane & 15)) * PITCHB + (lane >> 4) * 16);
    const int b_n0 = warp_n + (lane & 7) + ((lane >> 4) << 3);
    const uint32_t b_lane_off =
        (uint32_t)(b_n0 * PITCHB + ((lane >> 3) & 1) * 16);

    for (int ch = 0; ch < NCHUNK; ch++) {
        cp_wait0();
        __syncthreads();            // single barrier per chunk
        if (ch + 1 < NCHUNK) issue(ch + 1, (ch + 1) & 1);
        cp_commit();

        const uint32_t sbase = sb + (ch & 1) * STAGEB;
        #pragma unroll
        for (int s16 = 0; s16 < 4; s16++) {
            const uint32_t kb = (uint32_t)(s16 * 32);   // 16 bf16 = 32B
            uint32_t ah[4][4], al[4][4];
            #pragma unroll
            for (int m = 0; m < 4; m++) {
                const uint32_t off = a_lane_off + (uint32_t)(m * 16 * PITCHB) + kb;
                ldm_x4(ah[m], sbase + SA_H + off);
                ldm_x4(al[m], sbase + SA_L + off);
            }
            #pragma unroll
            for (int np = 0; np < 4; np++) {            // 4 x 16-col B blocks
                const uint32_t off = b_lane_off + (uint32_t)(np * 16 * PITCHB) + kb;
                uint32_t th[4], tl[4];
                ldm_x4(th, sbase + SB_H + off);
                ldm_x4(tl, sbase + SB_L + off);
                #pragma unroll
                for (int m = 0; m < 4; m++) {
                    mma16816(acc[m][np * 2],     ah[m], th);
                    mma16816(acc[m][np * 2],     ah[m], tl);
                    mma16816(acc[m][np * 2],     al[m], th);
                    mma16816(acc[m][np * 2 + 1], ah[m], th + 2);
                    mma16816(acc[m][np * 2 + 1], ah[m], tl + 2);
                    mma16816(acc[m][np * 2 + 1], al[m], th + 2);
                }
            }
        }
    }

    // Epilogue: add bias, store fp32.
    const int erow = lane >> 2;
    const int ecol = (lane & 3) * 2;
    #pragma unroll
    for (int m = 0; m < 4; m++) {
        const size_t row = (size_t)(bm + warp_m + m * 16 + erow);
        #pragma unroll
        for (int n = 0; n < 8; n++) {
            const int col = bn + warp_n + n * 8 + ecol;
            const float bx = bias[col], by = bias[col + 1];
            float2 o0 = make_float2(acc[m][n][0] + bx, acc[m][n][1] + by);
            float2 o1 = make_float2(acc[m][n][2] + bx, acc[m][n][3] + by);
            *reinterpret_cast<float2*>(C + row * OUT_DIM + col) = o0;
            *reinterpret_cast<float2*>(C + (row + 8) * OUT_DIM + col) = o1;
        }
    }
}

// ---------------------------------------------------------------------------
// Launch
// ---------------------------------------------------------------------------
extern "C" void kernel_launch(void* const* d_in, const int* in_sizes, int n_in,
                              void* d_out, int out_size)
{
    const float* x         = (const float*)d_in[0];      // [4,2048,4096]
    const float* centroids = (const float*)d_in[1];      // [256,8]
    const int*   labels    = (const int*)d_in[2];        // [2097152] int32
    const float* scale     = (const float*)d_in[3];      // [4096]
    const float* bias      = (const float*)d_in[4];      // [4096]
    float*       out       = (float*)d_out;              // [8192,4096]

    (void)in_sizes; (void)n_in; (void)out_size;

    cudaFuncSetAttribute(gemm_mma_kernel,
                         cudaFuncAttributeMaxDynamicSharedMemorySize, SMEM_TOTAL);

    decompress_split_kernel<<<(OUT_DIM * IN_DIM / CB_BLK) / 256, 256>>>(labels, centroids, scale);
    split_x_kernel<<<(int)(((size_t)M_DIM * IN_DIM / 4) / 256), 256>>>(x);

    dim3 grid(OUT_DIM / BN, M_DIM / BM);   // (16, 64)
    gemm_mma_kernel<<<grid, 256, SMEM_TOTAL>>>(bias, out);
}

// round 8
// speedup vs baseline: 4.9628x; 1.5847x over previous
#include <cuda_runtime.h>
#include <cuda_fp16.h>
#include <cstdint>

#define OUT_DIM 4096
#define IN_DIM  4096
#define M_DIM   8192
#define CB_BLK  8

// ---- GEMM tiling ----
#define BM 128
#define BN 256
#define BK 64
#define NCHUNK (IN_DIM / BK)      // 64
#define PITCHB 144                // bytes per smem row (128 data + 16 pad)
#define ATILE  (128 * PITCHB)     // 18432
#define BTILE  (256 * PITCHB)     // 36864
#define SA_OFF 0
#define SB_OFF (ATILE)
#define STAGEB (ATILE + BTILE)    // 55296
#define NSTAGE 3
#define SMEM_TOTAL (NSTAGE * STAGEB)   // 165888 (162 KB)

// fp16 copies (static device scratch; allocation-guard safe)
__device__ __align__(16) __half g_Wf[(size_t)OUT_DIM * IN_DIM];
__device__ __align__(16) __half g_xf[(size_t)M_DIM * IN_DIM];

// ---------------------------------------------------------------------------
// helpers
// ---------------------------------------------------------------------------
__device__ __forceinline__ uint32_t smem_u32(const void* p) {
    uint32_t a;
    asm("{ .reg .u64 t; cvta.to.shared.u64 t, %1; cvt.u32.u64 %0, t; }" : "=r"(a) : "l"(p));
    return a;
}
__device__ __forceinline__ void cp16(uint32_t saddr, const void* gaddr) {
    asm volatile("cp.async.cg.shared.global [%0], [%1], 16;" :: "r"(saddr), "l"(gaddr));
}
__device__ __forceinline__ void cp_commit() {
    asm volatile("cp.async.commit_group;" ::: "memory");
}
__device__ __forceinline__ void cp_wait1() {
    asm volatile("cp.async.wait_group 1;" ::: "memory");
}
__device__ __forceinline__ void ldm_x4(uint32_t* r, uint32_t addr) {
    asm volatile("ldmatrix.sync.aligned.m8n8.x4.shared.b16 {%0,%1,%2,%3}, [%4];"
                 : "=r"(r[0]), "=r"(r[1]), "=r"(r[2]), "=r"(r[3]) : "r"(addr));
}
__device__ __forceinline__ void mma16816(float* c, const uint32_t* a, const uint32_t* b) {
    asm volatile(
        "mma.sync.aligned.m16n8k16.row.col.f32.f16.f16.f32 "
        "{%0,%1,%2,%3}, {%4,%5,%6,%7}, {%8,%9}, {%0,%1,%2,%3};"
        : "+f"(c[0]), "+f"(c[1]), "+f"(c[2]), "+f"(c[3])
        : "r"(a[0]), "r"(a[1]), "r"(a[2]), "r"(a[3]), "r"(b[0]), "r"(b[1]));
}

// ---------------------------------------------------------------------------
// Prep 1: VQ decompress + fold scale -> fp16 W
// ---------------------------------------------------------------------------
__global__ void __launch_bounds__(256) decompress_kernel(
    const int* __restrict__ labels,
    const float* __restrict__ centroids,
    const float* __restrict__ scale)
{
    int j = blockIdx.x * blockDim.x + threadIdx.x;   // 0 .. 2097151
    int lab = labels[j] & 0xFF;
    const float4* c = reinterpret_cast<const float4*>(centroids + (size_t)lab * CB_BLK);
    float4 c0 = c[0], c1 = c[1];
    int k = (j * CB_BLK) & (IN_DIM - 1);
    const float4* s = reinterpret_cast<const float4*>(scale + k);
    float4 s0 = s[0], s1 = s[1];
    float w[8] = { c0.x * s0.x, c0.y * s0.y, c0.z * s0.z, c0.w * s0.w,
                   c1.x * s1.x, c1.y * s1.y, c1.z * s1.z, c1.w * s1.w };
    __align__(16) __half h[8];
    #pragma unroll
    for (int t = 0; t < 8; t++) h[t] = __float2half_rn(w[t]);
    *reinterpret_cast<uint4*>(&g_Wf[(size_t)j * CB_BLK]) = *reinterpret_cast<uint4*>(h);
}

// ---------------------------------------------------------------------------
// Prep 2: x -> fp16
// ---------------------------------------------------------------------------
__global__ void __launch_bounds__(256) cvt_x_kernel(const float* __restrict__ x)
{
    size_t i = (size_t)blockIdx.x * blockDim.x + threadIdx.x;   // float4 index
    float4 v = reinterpret_cast<const float4*>(x)[i];
    __align__(8) __half h[4];
    h[0] = __float2half_rn(v.x); h[1] = __float2half_rn(v.y);
    h[2] = __float2half_rn(v.z); h[3] = __float2half_rn(v.w);
    *reinterpret_cast<uint2*>(&g_xf[i * 4]) = *reinterpret_cast<uint2*>(h);
}

// ---------------------------------------------------------------------------
// Single-pass fp16 GEMM (fp32 accum): C = xf @ Wf^T + bias
// 128x256 CTA tile, BK=64, 3-stage cp.async pipeline (wait_group 1),
// one barrier per chunk, 8 warps of 64x64.
// ---------------------------------------------------------------------------
__global__ void __launch_bounds__(256, 1) gemm_mma_kernel(
    const float* __restrict__ bias,
    float* __restrict__ C)
{
    extern __shared__ char smem[];
    const uint32_t sb = smem_u32(smem);
    const int tid  = threadIdx.x;
    const int wid  = tid >> 5;
    const int lane = tid & 31;
    const int bm = blockIdx.y * BM;
    const int bn = blockIdx.x * BN;
    const int warp_m = (wid >> 2) * 64;     // 0 or 64
    const int warp_n = (wid & 3) * 64;      // 0,64,128,192

    float acc[4][8][4];
    #pragma unroll
    for (int m = 0; m < 4; m++)
        #pragma unroll
        for (int n = 0; n < 8; n++)
            #pragma unroll
            for (int v = 0; v < 4; v++) acc[m][n][v] = 0.0f;

    // one stage: A 128 rows + B 256 rows, 128B/row; 12 cp16 per thread
    auto issue = [&](int ch, int stg) {
        const int k0 = ch * BK;
        const uint32_t sbase = sb + stg * STAGEB;
        #pragma unroll
        for (int i = 0; i < 4; i++) {
            const int u = tid + i * 256;
            const int r = u >> 3;              // 0..127
            const int c = u & 7;
            const uint32_t so = (uint32_t)(r * PITCHB + c * 16);
            cp16(sbase + SA_OFF + so, g_xf + (size_t)(bm + r) * IN_DIM + k0 + c * 8);
        }
        #pragma unroll
        for (int i = 0; i < 8; i++) {
            const int u = tid + i * 256;
            const int r = u >> 3;              // 0..255
            const int c = u & 7;
            const uint32_t so = (uint32_t)(r * PITCHB + c * 16);
            cp16(sbase + SB_OFF + so, g_Wf + (size_t)(bn + r) * IN_DIM + k0 + c * 8);
        }
    };

    issue(0, 0); cp_commit();
    issue(1, 1); cp_commit();

    // ldmatrix lane addressing (byte offsets within a tile)
    const uint32_t a_lane_off =
        (uint32_t)((warp_m + (lane & 15)) * PITCHB + (lane >> 4) * 16);
    const int b_n0 = warp_n + (lane & 7) + ((lane >> 4) << 3);
    const uint32_t b_lane_off =
        (uint32_t)(b_n0 * PITCHB + ((lane >> 3) & 1) * 16);

    int stg = 0;
    for (int ch = 0; ch < NCHUNK; ch++) {
        cp_wait1();                 // chunk ch resident; ch+1 may still be in flight
        __syncthreads();            // single barrier per chunk
        if (ch + 2 < NCHUNK) {
            int nstg = stg + 2; if (nstg >= NSTAGE) nstg -= NSTAGE;
            issue(ch + 2, nstg);
        }
        cp_commit();

        const uint32_t sbase = sb + stg * STAGEB;
        #pragma unroll
        for (int s16 = 0; s16 < 4; s16++) {
            const uint32_t kb = (uint32_t)(s16 * 32);   // 16 fp16 = 32B
            uint32_t ah[4][4];
            #pragma unroll
            for (int m = 0; m < 4; m++) {
                const uint32_t off = a_lane_off + (uint32_t)(m * 16 * PITCHB) + kb;
                ldm_x4(ah[m], sbase + SA_OFF + off);
            }
            #pragma unroll
            for (int np = 0; np < 4; np++) {            // 4 x 16-col B blocks
                const uint32_t off = b_lane_off + (uint32_t)(np * 16 * PITCHB) + kb;
                uint32_t th[4];
                ldm_x4(th, sbase + SB_OFF + off);
                #pragma unroll
                for (int m = 0; m < 4; m++) {
                    mma16816(acc[m][np * 2],     ah[m], th);
                    mma16816(acc[m][np * 2 + 1], ah[m], th + 2);
                }
            }
        }
        if (++stg == NSTAGE) stg = 0;
    }

    // Epilogue: add bias, store fp32.
    const int erow = lane >> 2;
    const int ecol = (lane & 3) * 2;
    #pragma unroll
    for (int m = 0; m < 4; m++) {
        const size_t row = (size_t)(bm + warp_m + m * 16 + erow);
        #pragma unroll
        for (int n = 0; n < 8; n++) {
            const int col = bn + warp_n + n * 8 + ecol;
            const float bx = bias[col], by = bias[col + 1];
            float2 o0 = make_float2(acc[m][n][0] + bx, acc[m][n][1] + by);
            float2 o1 = make_float2(acc[m][n][2] + bx, acc[m][n][3] + by);
            *reinterpret_cast<float2*>(C + row * OUT_DIM + col) = o0;
            *reinterpret_cast<float2*>(C + (row + 8) * OUT_DIM + col) = o1;
        }
    }
}

// ---------------------------------------------------------------------------
// Launch
// ---------------------------------------------------------------------------
extern "C" void kernel_launch(void* const* d_in, const int* in_sizes, int n_in,
                              void* d_out, int out_size)
{
    const float* x         = (const float*)d_in[0];      // [4,2048,4096]
    const float* centroids = (const float*)d_in[1];      // [256,8]
    const int*   labels    = (const int*)d_in[2];        // [2097152] int32
    const float* scale     = (const float*)d_in[3];      // [4096]
    const float* bias      = (const float*)d_in[4];      // [4096]
    float*       out       = (float*)d_out;              // [8192,4096]

    (void)in_sizes; (void)n_in; (void)out_size;

    cudaFuncSetAttribute(gemm_mma_kernel,
                         cudaFuncAttributeMaxDynamicSharedMemorySize, SMEM_TOTAL);

    decompress_kernel<<<(OUT_DIM * IN_DIM / CB_BLK) / 256, 256>>>(labels, centroids, scale);
    cvt_x_kernel<<<(int)(((size_t)M_DIM * IN_DIM / 4) / 256), 256>>>(x);

    dim3 grid(OUT_DIM / BN, M_DIM / BM);   // (16, 64)
    gemm_mma_kernel<<<grid, 256, SMEM_TOTAL>>>(bias, out);
}

// round 9
// speedup vs baseline: 7.8916x; 1.5901x over previous
#include <cuda_runtime.h>
#include <cuda_fp16.h>
#include <cstdint>

#define OUT_DIM 4096
#define IN_DIM  4096
#define M_DIM   8192
#define CB_BLK  8

// ---- GEMM tiling ----
#define BM 128
#define BN 256
#define BK 64
#define NCHUNK (IN_DIM / BK)      // 64
#define NTHREADS 512
#define PITCHB 144                // bytes per smem row (128 data + 16 pad)
#define ATILE  (128 * PITCHB)     // 18432
#define BTILE  (256 * PITCHB)     // 36864
#define SA_OFF 0
#define SB_OFF (ATILE)
#define STAGEB (ATILE + BTILE)    // 55296
#define NSTAGE 4
#define SMEM_TOTAL (NSTAGE * STAGEB)   // 221184 (216 KB)

// fp16 copies (static device scratch; allocation-guard safe)
__device__ __align__(16) __half g_Wf[(size_t)OUT_DIM * IN_DIM];
__device__ __align__(16) __half g_xf[(size_t)M_DIM * IN_DIM];

// ---------------------------------------------------------------------------
// helpers
// ---------------------------------------------------------------------------
__device__ __forceinline__ uint32_t smem_u32(const void* p) {
    uint32_t a;
    asm("{ .reg .u64 t; cvta.to.shared.u64 t, %1; cvt.u32.u64 %0, t; }" : "=r"(a) : "l"(p));
    return a;
}
__device__ __forceinline__ void cp16(uint32_t saddr, const void* gaddr) {
    asm volatile("cp.async.cg.shared.global [%0], [%1], 16;" :: "r"(saddr), "l"(gaddr));
}
__device__ __forceinline__ void cp_commit() {
    asm volatile("cp.async.commit_group;" ::: "memory");
}
__device__ __forceinline__ void cp_wait2() {
    asm volatile("cp.async.wait_group 2;" ::: "memory");
}
__device__ __forceinline__ void ldm_x4(uint32_t* r, uint32_t addr) {
    asm volatile("ldmatrix.sync.aligned.m8n8.x4.shared.b16 {%0,%1,%2,%3}, [%4];"
                 : "=r"(r[0]), "=r"(r[1]), "=r"(r[2]), "=r"(r[3]) : "r"(addr));
}
__device__ __forceinline__ void mma16816(float* c, const uint32_t* a, const uint32_t* b) {
    asm volatile(
        "mma.sync.aligned.m16n8k16.row.col.f32.f16.f16.f32 "
        "{%0,%1,%2,%3}, {%4,%5,%6,%7}, {%8,%9}, {%0,%1,%2,%3};"
        : "+f"(c[0]), "+f"(c[1]), "+f"(c[2]), "+f"(c[3])
        : "r"(a[0]), "r"(a[1]), "r"(a[2]), "r"(a[3]), "r"(b[0]), "r"(b[1]));
}

// ---------------------------------------------------------------------------
// Prep 1: VQ decompress + fold scale -> fp16 W
// ---------------------------------------------------------------------------
__global__ void __launch_bounds__(256) decompress_kernel(
    const int* __restrict__ labels,
    const float* __restrict__ centroids,
    const float* __restrict__ scale)
{
    int j = blockIdx.x * blockDim.x + threadIdx.x;   // 0 .. 2097151
    int lab = labels[j] & 0xFF;
    const float4* c = reinterpret_cast<const float4*>(centroids + (size_t)lab * CB_BLK);
    float4 c0 = c[0], c1 = c[1];
    int k = (j * CB_BLK) & (IN_DIM - 1);
    const float4* s = reinterpret_cast<const float4*>(scale + k);
    float4 s0 = s[0], s1 = s[1];
    float w[8] = { c0.x * s0.x, c0.y * s0.y, c0.z * s0.z, c0.w * s0.w,
                   c1.x * s1.x, c1.y * s1.y, c1.z * s1.z, c1.w * s1.w };
    __align__(16) __half h[8];
    #pragma unroll
    for (int t = 0; t < 8; t++) h[t] = __float2half_rn(w[t]);
    *reinterpret_cast<uint4*>(&g_Wf[(size_t)j * CB_BLK]) = *reinterpret_cast<uint4*>(h);
}

// ---------------------------------------------------------------------------
// Prep 2: x -> fp16
// ---------------------------------------------------------------------------
__global__ void __launch_bounds__(256) cvt_x_kernel(const float* __restrict__ x)
{
    size_t i = (size_t)blockIdx.x * blockDim.x + threadIdx.x;   // float4 index
    float4 v = reinterpret_cast<const float4*>(x)[i];
    __align__(8) __half h[4];
    h[0] = __float2half_rn(v.x); h[1] = __float2half_rn(v.y);
    h[2] = __float2half_rn(v.z); h[3] = __float2half_rn(v.w);
    *reinterpret_cast<uint2*>(&g_xf[i * 4]) = *reinterpret_cast<uint2*>(h);
}

// ---------------------------------------------------------------------------
// Single-pass fp16 GEMM (fp32 accum): C = xf @ Wf^T + bias
// 128x256 CTA tile, BK=64, 4-stage cp.async pipeline (wait_group 2),
// one barrier per chunk, 16 warps (2x8 grid) of 64x32 -> 4 warps/SMSP
// to hide ldmatrix->mma and cp.async wait stalls.
// ---------------------------------------------------------------------------
__global__ void __launch_bounds__(NTHREADS, 1) gemm_mma_kernel(
    const float* __restrict__ bias,
    float* __restrict__ C)
{
    extern __shared__ char smem[];
    const uint32_t sb = smem_u32(smem);
    const int tid  = threadIdx.x;
    const int wid  = tid >> 5;
    const int lane = tid & 31;
    const int bm = blockIdx.y * BM;
    const int bn = blockIdx.x * BN;
    const int warp_m = (wid >> 3) * 64;     // 0 or 64
    const int warp_n = (wid & 7) * 32;      // 0,32,...,224

    float acc[4][4][4];
    #pragma unroll
    for (int m = 0; m < 4; m++)
        #pragma unroll
        for (int n = 0; n < 4; n++)
            #pragma unroll
            for (int v = 0; v < 4; v++) acc[m][n][v] = 0.0f;

    // one stage: A 128 rows + B 256 rows, 128B/row; 6 cp16 per thread
    auto issue = [&](int ch, int stg) {
        const int k0 = ch * BK;
        const uint32_t sbase = sb + stg * STAGEB;
        #pragma unroll
        for (int i = 0; i < 2; i++) {
            const int u = tid + i * NTHREADS;
            const int r = u >> 3;              // 0..127
            const int c = u & 7;
            const uint32_t so = (uint32_t)(r * PITCHB + c * 16);
            cp16(sbase + SA_OFF + so, g_xf + (size_t)(bm + r) * IN_DIM + k0 + c * 8);
        }
        #pragma unroll
        for (int i = 0; i < 4; i++) {
            const int u = tid + i * NTHREADS;
            const int r = u >> 3;              // 0..255
            const int c = u & 7;
            const uint32_t so = (uint32_t)(r * PITCHB + c * 16);
            cp16(sbase + SB_OFF + so, g_Wf + (size_t)(bn + r) * IN_DIM + k0 + c * 8);
        }
    };

    issue(0, 0); cp_commit();
    issue(1, 1); cp_commit();
    issue(2, 2); cp_commit();

    // ldmatrix lane addressing (byte offsets within a tile)
    const uint32_t a_lane_off =
        (uint32_t)((warp_m + (lane & 15)) * PITCHB + (lane >> 4) * 16);
    const int b_n0 = warp_n + (lane & 7) + ((lane >> 4) << 3);
    const uint32_t b_lane_off =
        (uint32_t)(b_n0 * PITCHB + ((lane >> 3) & 1) * 16);

    int stg = 0;
    for (int ch = 0; ch < NCHUNK; ch++) {
        cp_wait2();                 // chunk ch resident; ch+1, ch+2 may be in flight
        __syncthreads();            // single barrier per chunk
        if (ch + 3 < NCHUNK) {
            int nstg = stg + 3; if (nstg >= NSTAGE) nstg -= NSTAGE;
            issue(ch + 3, nstg);
        }
        cp_commit();

        const uint32_t sbase = sb + stg * STAGEB;
        #pragma unroll
        for (int s16 = 0; s16 < 4; s16++) {
            const uint32_t kb = (uint32_t)(s16 * 32);   // 16 fp16 = 32B
            uint32_t ah[4][4];
            #pragma unroll
            for (int m = 0; m < 4; m++) {
                const uint32_t off = a_lane_off + (uint32_t)(m * 16 * PITCHB) + kb;
                ldm_x4(ah[m], sbase + SA_OFF + off);
            }
            #pragma unroll
            for (int np = 0; np < 2; np++) {            // 2 x 16-col B blocks
                const uint32_t off = b_lane_off + (uint32_t)(np * 16 * PITCHB) + kb;
                uint32_t th[4];
                ldm_x4(th, sbase + SB_OFF + off);
                #pragma unroll
                for (int m = 0; m < 4; m++) {
                    mma16816(acc[m][np * 2],     ah[m], th);
                    mma16816(acc[m][np * 2 + 1], ah[m], th + 2);
                }
            }
        }
        if (++stg == NSTAGE) stg = 0;
    }

    // Epilogue: add bias, store fp32.
    const int erow = lane >> 2;
    const int ecol = (lane & 3) * 2;
    #pragma unroll
    for (int m = 0; m < 4; m++) {
        const size_t row = (size_t)(bm + warp_m + m * 16 + erow);
        #pragma unroll
        for (int n = 0; n < 4; n++) {
            const int col = bn + warp_n + n * 8 + ecol;
            const float bx = bias[col], by = bias[col + 1];
            float2 o0 = make_float2(acc[m][n][0] + bx, acc[m][n][1] + by);
            float2 o1 = make_float2(acc[m][n][2] + bx, acc[m][n][3] + by);
            *reinterpret_cast<float2*>(C + row * OUT_DIM + col) = o0;
            *reinterpret_cast<float2*>(C + (row + 8) * OUT_DIM + col) = o1;
        }
    }
}

// ---------------------------------------------------------------------------
// Launch
// ---------------------------------------------------------------------------
extern "C" void kernel_launch(void* const* d_in, const int* in_sizes, int n_in,
                              void* d_out, int out_size)
{
    const float* x         = (const float*)d_in[0];      // [4,2048,4096]
    const float* centroids = (const float*)d_in[1];      // [256,8]
    const int*   labels    = (const int*)d_in[2];        // [2097152] int32
    const float* scale     = (const float*)d_in[3];      // [4096]
    const float* bias      = (const float*)d_in[4];      // [4096]
    float*       out       = (float*)d_out;              // [8192,4096]

    (void)in_sizes; (void)n_in; (void)out_size;

    cudaFuncSetAttribute(gemm_mma_kernel,
                         cudaFuncAttributeMaxDynamicSharedMemorySize, SMEM_TOTAL);

    decompress_kernel<<<(OUT_DIM * IN_DIM / CB_BLK) / 256, 256>>>(labels, centroids, scale);
    cvt_x_kernel<<<(int)(((size_t)M_DIM * IN_DIM / 4) / 256), 256>>>(x);

    dim3 grid(OUT_DIM / BN, M_DIM / BM);   // (16, 64)
    gemm_mma_kernel<<<grid, NTHREADS, SMEM_TOTAL>>>(bias, out);
}

// round 10
// speedup vs baseline: 8.1867x; 1.0374x over previous
#include <cuda_runtime.h>
#include <cuda_fp16.h>
#include <cstdint>

#define OUT_DIM 4096
#define IN_DIM  4096
#define M_DIM   8192
#define CB_BLK  8

// ---- GEMM tiling ----
#define BM 128
#define BN 256
#define BK 128
#define NCHUNK (IN_DIM / BK)      // 32
#define NTHREADS 512
#define PITCHB 272                // bytes per smem row (256 data + 16 pad)
#define ATILE  (128 * PITCHB)     // 34816
#define BTILE  (256 * PITCHB)     // 69632
#define SA_OFF 0
#define SB_OFF (ATILE)
#define STAGEB (ATILE + BTILE)    // 104448
#define NSTAGE 2
#define SMEM_TOTAL (NSTAGE * STAGEB)   // 208896 (204 KB)

// fp16 copies (static device scratch; allocation-guard safe)
__device__ __align__(16) __half g_Wf[(size_t)OUT_DIM * IN_DIM];
__device__ __align__(16) __half g_xf[(size_t)M_DIM * IN_DIM];

// ---------------------------------------------------------------------------
// helpers
// ---------------------------------------------------------------------------
__device__ __forceinline__ uint32_t smem_u32(const void* p) {
    uint32_t a;
    asm("{ .reg .u64 t; cvta.to.shared.u64 t, %1; cvt.u32.u64 %0, t; }" : "=r"(a) : "l"(p));
    return a;
}
__device__ __forceinline__ void cp16(uint32_t saddr, const void* gaddr) {
    asm volatile("cp.async.cg.shared.global [%0], [%1], 16;" :: "r"(saddr), "l"(gaddr));
}
__device__ __forceinline__ void cp_commit() {
    asm volatile("cp.async.commit_group;" ::: "memory");
}
__device__ __forceinline__ void cp_wait0() {
    asm volatile("cp.async.wait_group 0;" ::: "memory");
}
__device__ __forceinline__ void ldm_x4(uint32_t* r, uint32_t addr) {
    asm volatile("ldmatrix.sync.aligned.m8n8.x4.shared.b16 {%0,%1,%2,%3}, [%4];"
                 : "=r"(r[0]), "=r"(r[1]), "=r"(r[2]), "=r"(r[3]) : "r"(addr));
}
__device__ __forceinline__ void mma16816(float* c, const uint32_t* a, const uint32_t* b) {
    asm volatile(
        "mma.sync.aligned.m16n8k16.row.col.f32.f16.f16.f32 "
        "{%0,%1,%2,%3}, {%4,%5,%6,%7}, {%8,%9}, {%0,%1,%2,%3};"
        : "+f"(c[0]), "+f"(c[1]), "+f"(c[2]), "+f"(c[3])
        : "r"(a[0]), "r"(a[1]), "r"(a[2]), "r"(a[3]), "r"(b[0]), "r"(b[1]));
}

// ---------------------------------------------------------------------------
// Prep 1: VQ decompress + fold scale -> fp16 W
// ---------------------------------------------------------------------------
__global__ void __launch_bounds__(256) decompress_kernel(
    const int* __restrict__ labels,
    const float* __restrict__ centroids,
    const float* __restrict__ scale)
{
    int j = blockIdx.x * blockDim.x + threadIdx.x;   // 0 .. 2097151
    int lab = labels[j] & 0xFF;
    const float4* c = reinterpret_cast<const float4*>(centroids + (size_t)lab * CB_BLK);
    float4 c0 = c[0], c1 = c[1];
    int k = (j * CB_BLK) & (IN_DIM - 1);
    const float4* s = reinterpret_cast<const float4*>(scale + k);
    float4 s0 = s[0], s1 = s[1];
    float w[8] = { c0.x * s0.x, c0.y * s0.y, c0.z * s0.z, c0.w * s0.w,
                   c1.x * s1.x, c1.y * s1.y, c1.z * s1.z, c1.w * s1.w };
    __align__(16) __half h[8];
    #pragma unroll
    for (int t = 0; t < 8; t++) h[t] = __float2half_rn(w[t]);
    *reinterpret_cast<uint4*>(&g_Wf[(size_t)j * CB_BLK]) = *reinterpret_cast<uint4*>(h);
}

// ---------------------------------------------------------------------------
// Prep 2: x -> fp16
// ---------------------------------------------------------------------------
__global__ void __launch_bounds__(256) cvt_x_kernel(const float* __restrict__ x)
{
    size_t i = (size_t)blockIdx.x * blockDim.x + threadIdx.x;   // float4 index
    float4 v = reinterpret_cast<const float4*>(x)[i];
    __align__(8) __half h[4];
    h[0] = __float2half_rn(v.x); h[1] = __float2half_rn(v.y);
    h[2] = __float2half_rn(v.z); h[3] = __float2half_rn(v.w);
    *reinterpret_cast<uint2*>(&g_xf[i * 4]) = *reinterpret_cast<uint2*>(h);
}

// ---------------------------------------------------------------------------
// Single-pass fp16 GEMM (fp32 accum): C = xf @ Wf^T + bias
// 128x256 CTA tile, BK=128 (32 chunks -> half the barrier/wait events),
// 2-stage cp.async pipeline, one barrier per chunk, 16 warps of 64x32.
// ---------------------------------------------------------------------------
__global__ void __launch_bounds__(NTHREADS, 1) gemm_mma_kernel(
    const float* __restrict__ bias,
    float* __restrict__ C)
{
    extern __shared__ char smem[];
    const uint32_t sb = smem_u32(smem);
    const int tid  = threadIdx.x;
    const int wid  = tid >> 5;
    const int lane = tid & 31;
    const int bm = blockIdx.y * BM;
    const int bn = blockIdx.x * BN;
    const int warp_m = (wid >> 3) * 64;     // 0 or 64
    const int warp_n = (wid & 7) * 32;      // 0,32,...,224

    float acc[4][4][4];
    #pragma unroll
    for (int m = 0; m < 4; m++)
        #pragma unroll
        for (int n = 0; n < 4; n++)
            #pragma unroll
            for (int v = 0; v < 4; v++) acc[m][n][v] = 0.0f;

    // one stage: A 128 rows + B 256 rows, 256B/row; 12 cp16 per thread
    auto issue = [&](int ch, int stg) {
        const int k0 = ch * BK;
        const uint32_t sbase = sb + stg * STAGEB;
        #pragma unroll
        for (int i = 0; i < 4; i++) {
            const int u = tid + i * NTHREADS;
            const int r = u >> 4;              // 0..127
            const int c = u & 15;              // 16B segment 0..15
            const uint32_t so = (uint32_t)(r * PITCHB + c * 16);
            cp16(sbase + SA_OFF + so, g_xf + (size_t)(bm + r) * IN_DIM + k0 + c * 8);
        }
        #pragma unroll
        for (int i = 0; i < 8; i++) {
            const int u = tid + i * NTHREADS;
            const int r = u >> 4;              // 0..255
            const int c = u & 15;
            const uint32_t so = (uint32_t)(r * PITCHB + c * 16);
            cp16(sbase + SB_OFF + so, g_Wf + (size_t)(bn + r) * IN_DIM + k0 + c * 8);
        }
    };

    issue(0, 0);
    cp_commit();

    // ldmatrix lane addressing (byte offsets within a tile)
    const uint32_t a_lane_off =
        (uint32_t)((warp_m + (lane & 15)) * PITCHB + (lane >> 4) * 16);
    const int b_n0 = warp_n + (lane & 7) + ((lane >> 4) << 3);
    const uint32_t b_lane_off =
        (uint32_t)(b_n0 * PITCHB + ((lane >> 3) & 1) * 16);

    for (int ch = 0; ch < NCHUNK; ch++) {
        cp_wait0();
        __syncthreads();            // single barrier per chunk
        if (ch + 1 < NCHUNK) issue(ch + 1, (ch + 1) & 1);
        cp_commit();

        const uint32_t sbase = sb + (ch & 1) * STAGEB;
        #pragma unroll
        for (int s16 = 0; s16 < 8; s16++) {
            const uint32_t kb = (uint32_t)(s16 * 32);   // 16 fp16 = 32B
            uint32_t ah[4][4];
            #pragma unroll
            for (int m = 0; m < 4; m++) {
                const uint32_t off = a_lane_off + (uint32_t)(m * 16 * PITCHB) + kb;
                ldm_x4(ah[m], sbase + SA_OFF + off);
            }
            #pragma unroll
            for (int np = 0; np < 2; np++) {            // 2 x 16-col B blocks
                const uint32_t off = b_lane_off + (uint32_t)(np * 16 * PITCHB) + kb;
                uint32_t th[4];
                ldm_x4(th, sbase + SB_OFF + off);
                #pragma unroll
                for (int m = 0; m < 4; m++) {
                    mma16816(acc[m][np * 2],     ah[m], th);
                    mma16816(acc[m][np * 2 + 1], ah[m], th + 2);
                }
            }
        }
    }

    // Epilogue: add bias, store fp32.
    const int erow = lane >> 2;
    const int ecol = (lane & 3) * 2;
    #pragma unroll
    for (int m = 0; m < 4; m++) {
        const size_t row = (size_t)(bm + warp_m + m * 16 + erow);
        #pragma unroll
        for (int n = 0; n < 4; n++) {
            const int col = bn + warp_n + n * 8 + ecol;
            const float bx = bias[col], by = bias[col + 1];
            float2 o0 = make_float2(acc[m][n][0] + bx, acc[m][n][1] + by);
            float2 o1 = make_float2(acc[m][n][2] + bx, acc[m][n][3] + by);
            *reinterpret_cast<float2*>(C + row * OUT_DIM + col) = o0;
            *reinterpret_cast<float2*>(C + (row + 8) * OUT_DIM + col) = o1;
        }
    }
}

// ---------------------------------------------------------------------------
// Launch
// ---------------------------------------------------------------------------
extern "C" void kernel_launch(void* const* d_in, const int* in_sizes, int n_in,
                              void* d_out, int out_size)
{
    const float* x         = (const float*)d_in[0];      // [4,2048,4096]
    const float* centroids = (const float*)d_in[1];      // [256,8]
    const int*   labels    = (const int*)d_in[2];        // [2097152] int32
    const float* scale     = (const float*)d_in[3];      // [4096]
    const float* bias      = (const float*)d_in[4];      // [4096]
    float*       out       = (float*)d_out;              // [8192,4096]

    (void)in_sizes; (void)n_in; (void)out_size;

    cudaFuncSetAttribute(gemm_mma_kernel,
                         cudaFuncAttributeMaxDynamicSharedMemorySize, SMEM_TOTAL);

    decompress_kernel<<<(OUT_DIM * IN_DIM / CB_BLK) / 256, 256>>>(labels, centroids, scale);
    cvt_x_kernel<<<(int)(((size_t)M_DIM * IN_DIM / 4) / 256), 256>>>(x);

    dim3 grid(OUT_DIM / BN, M_DIM / BM);   // (16, 64)
    gemm_mma_kernel<<<grid, NTHREADS, SMEM_TOTAL>>>(bias, out);
}